// round 16
// baseline (speedup 1.0000x reference)
#include <cuda_runtime.h>

// GCN_75050258530542 — round 16: scatter 16 edges/group (int4 index loads,
// two 8-edge half-batches), degree 16 edges/thread, k_out weights direct to
// registers (no sW smem). Structure otherwise R15.
// out[n,:] = rsqrt(deg_in[n]) * (sum_{e:dst=n} x[src,15:25]*rsqrt(deg_out[src])) @ (W1@W2)
//            + (b1@W2 + b2)

constexpr int NMAX = 100000;
constexpr int FP   = 16;   // 64B rows, 128B-aligned: 4-lane group hits 1 line

__device__ int g_deg_out[NMAX];
__device__ __align__(128) float g_xsn[NMAX * FP];   // slots 0-9 = x[:,15:25]*norm_s; pad 0
__device__ __align__(128) float g_agg[NMAX * FP];   // slots 0-9 sums, slot 10 = deg_in
__device__ float g_Weff[640];                       // W1@W2 (10 x 64)
__device__ float g_beff[64];                        // b1@W2 + b2

// ---------------------------------------------------------------- degrees + weff (last block)
__global__ void k_deg_weff(const int* __restrict__ src, int E,
                           const float* __restrict__ W1, const float* __restrict__ b1,
                           const float* __restrict__ W2, const float* __restrict__ b2) {
    int nb = gridDim.x - 1;
    if ((int)blockIdx.x == nb) {
        for (int idx = threadIdx.x; idx < 704; idx += blockDim.x) {
            if (idx < 640) {
                int i = idx >> 6, j = idx & 63;
                float s = 0.f;
#pragma unroll 8
                for (int k = 0; k < 128; k++) s += W1[i * 128 + k] * W2[k * 64 + j];
                g_Weff[idx] = s;
            } else {
                int j = idx - 640;
                float s = b2[j];
#pragma unroll 8
                for (int k = 0; k < 128; k++) s += b1[k] * W2[k * 64 + j];
                g_beff[j] = s;
            }
        }
        return;
    }
    // 16 edges per thread: 4 int4 loads
    int n16 = E >> 4;
    int stride = nb * blockDim.x;
    for (int t = blockIdx.x * blockDim.x + threadIdx.x; t < n16; t += stride) {
        const int4* s4 = reinterpret_cast<const int4*>(src) + 4 * t;
#pragma unroll
        for (int u = 0; u < 4; u++) {
            int4 s = s4[u];
            atomicAdd(&g_deg_out[s.x], 1);
            atomicAdd(&g_deg_out[s.y], 1);
            atomicAdd(&g_deg_out[s.z], 1);
            atomicAdd(&g_deg_out[s.w], 1);
        }
    }
    if (blockIdx.x == 0 && threadIdx.x == 0) {
        for (int e = (n16 << 4); e < E; e++) atomicAdd(&g_deg_out[src[e]], 1);
    }
}

// ---------------------------------------------------------------- prep: xsn = x[:,15:25]*norm_s + cleanup
__global__ void k_prep(const float* __restrict__ x, int N) {
    int i = blockIdx.x * blockDim.x + threadIdx.x;
    if (i >= N) return;
    int dout = g_deg_out[i];
    g_deg_out[i] = 0;                                   // self-clean (last reader)
    float ns = rsqrtf(dout > 0 ? (float)dout : 1.f);
    const float* base = x + (size_t)i * 40;
    float4 L0 = *reinterpret_cast<const float4*>(base + 12);
    float4 L1 = *reinterpret_cast<const float4*>(base + 16);
    float4 L2 = *reinterpret_cast<const float4*>(base + 20);
    float4 L3 = *reinterpret_cast<const float4*>(base + 24);
    float* o = g_xsn + (size_t)i * FP;
    *reinterpret_cast<float4*>(o)     = make_float4(L0.w * ns, L1.x * ns, L1.y * ns, L1.z * ns); // c15-18
    *reinterpret_cast<float4*>(o + 4) = make_float4(L1.w * ns, L2.x * ns, L2.y * ns, L2.z * ns); // c19-22
    *reinterpret_cast<float4*>(o + 8) = make_float4(L2.w * ns, L3.x * ns, 0.f, 0.f);             // c23-24, pad
    float4 z = {0.f, 0.f, 0.f, 0.f};
    float4* a = reinterpret_cast<float4*>(g_agg + (size_t)i * FP);
    a[0] = z; a[1] = z; a[2] = z; a[3] = z;
}

// ---------------------------------------------------------------- vector RED
__device__ __forceinline__ void red4(float* p, float a, float b, float c, float d) {
    asm volatile("red.global.add.v4.f32 [%0], {%1,%2,%3,%4};"
                 :: "l"(p), "f"(a), "f"(b), "f"(c), "f"(d) : "memory");
}

// ---------------------------------------------------------------- scatter: 4 lanes/edge, 16 edges/group
__global__ void __launch_bounds__(256) k_scatter(const int* __restrict__ src,
                                                 const int* __restrict__ dst, int E) {
    int tid = blockIdx.x * blockDim.x + threadIdx.x;
    int g = tid >> 2;          // edge group (16 edges)
    int q = tid & 3;           // quarter within feature row
    long base = (long)g * 16;
    if (base >= E) return;

    unsigned am = 0xffffffffu;
    int lq = (tid & 31) & ~3;  // group leader lane offset in warp
    int full = (base + 16 <= (long)E);

    if (full) {
        // lane q loads edges [4q, 4q+3] of the 16 as int4 (coalesced 16B)
        int4 sv = *reinterpret_cast<const int4*>(src + base + 4 * q);
        int4 dv = *reinterpret_cast<const int4*>(dst + base + 4 * q);
        int sa[4] = {sv.x, sv.y, sv.z, sv.w};
        int da[4] = {dv.x, dv.y, dv.z, dv.w};

#pragma unroll
        for (int h = 0; h < 2; h++) {              // two 8-edge half-batches
            int dd[8];
            float4 v[8];
#pragma unroll
            for (int j = 0; j < 8; j++) {
                int e = h * 8 + j;                 // edge index 0..15
                int owner = lq + (e >> 2);         // lane holding this edge
                int comp = e & 3;
                int sj = __shfl_sync(am, sa[comp], owner);
                dd[j]  = __shfl_sync(am, da[comp], owner);
                if (q < 3) v[j] = *reinterpret_cast<const float4*>(g_xsn + (size_t)sj * FP + q * 4);
            }
#pragma unroll
            for (int j = 0; j < 8; j++) {
                if (q < 3) {
                    float4 p = v[j];
                    if (q == 2) { p.z = 1.0f; p.w = 0.0f; }   // slot 10 += 1 (deg_in)
                    red4(g_agg + (size_t)dd[j] * FP + q * 4, p.x, p.y, p.z, p.w);
                }
            }
        }
    } else {
        int cnt = (int)(E - base);
        for (int j = 0; j < cnt; j++) {
            int sj = __ldg(src + base + j);
            int dj = __ldg(dst + base + j);
            if (q < 3) {
                float4 p = *reinterpret_cast<const float4*>(g_xsn + (size_t)sj * FP + q * 4);
                if (q == 2) { p.z = 1.0f; p.w = 0.0f; }
                red4(g_agg + (size_t)dj * FP + q * 4, p.x, p.y, p.z, p.w);
            }
        }
    }
}

// ---------------------------------------------------------------- k_out: 256-node smem tile, weights in regs
__global__ void __launch_bounds__(512) k_out(float* __restrict__ out, int N) {
    __shared__ __align__(16) float sAgg[256 * FP];   // 16KB tile
    int t = threadIdx.x;

    int tile = blockIdx.x * 256;
    int cnt = N - tile; if (cnt > 256) cnt = 256;
    int nq = cnt * 4;

    {
        const float4* srcA = reinterpret_cast<const float4*>(g_agg + (size_t)tile * FP);
        float4* dstA = reinterpret_cast<float4*>(sAgg);
        for (int k = t; k < nq; k += 512) dstA[k] = srcA[k];
    }

    int lane = t & 31;
    int warp = t >> 5;          // 16 warps
    // weights direct to registers: per k, the warp reads 32 consecutive floats (1 line)
    float w0[10], w1[10];
#pragma unroll
    for (int k = 0; k < 10; k++) {
        w0[k] = g_Weff[k * 64 + lane];
        w1[k] = g_Weff[k * 64 + 32 + lane];
    }
    float b0 = g_beff[lane];
    float b1 = g_beff[lane + 32];
    __syncthreads();

    for (int i = warp; i < cnt; i += 16) {
        const float4* r = reinterpret_cast<const float4*>(sAgg + i * FP);
        float4 a0 = r[0], a1 = r[1], a2 = r[2];   // LDS broadcast
        float nd = rsqrtf(a2.z > 0.f ? a2.z : 1.f);
        float s0 = a0.x * w0[0] + a0.y * w0[1] + a0.z * w0[2] + a0.w * w0[3]
                 + a1.x * w0[4] + a1.y * w0[5] + a1.z * w0[6] + a1.w * w0[7]
                 + a2.x * w0[8] + a2.y * w0[9];
        float s1 = a0.x * w1[0] + a0.y * w1[1] + a0.z * w1[2] + a0.w * w1[3]
                 + a1.x * w1[4] + a1.y * w1[5] + a1.z * w1[6] + a1.w * w1[7]
                 + a2.x * w1[8] + a2.y * w1[9];
        float* orow = out + (size_t)(tile + i) * 64;
        orow[lane]      = b0 + nd * s0;
        orow[lane + 32] = b1 + nd * s1;
    }
}

// ---------------------------------------------------------------- launch
extern "C" void kernel_launch(void* const* d_in, const int* in_sizes, int n_in,
                              void* d_out, int out_size) {
    const float* x   = (const float*)d_in[0];
    const int*   src = (const int*)d_in[1];
    const int*   dst = (const int*)d_in[2];
    const float* W1  = (const float*)d_in[3];
    const float* b1  = (const float*)d_in[4];
    const float* W2  = (const float*)d_in[5];
    const float* b2  = (const float*)d_in[6];
    float* out = (float*)d_out;

    int N = in_sizes[0] / 40;
    int E = in_sizes[1];

    // self-cleaning scratch: k_prep zeroes g_deg_out + g_agg before the scatter.

    int n16 = E >> 4;
    int db = (n16 > 0 ? (n16 + 255) / 256 : 1) + 1;        // +1 block for weff
    k_deg_weff<<<db, 256>>>(src, E, W1, b1, W2, b2);
    k_prep<<<(N + 255) / 256, 256>>>(x, N);

    long groups = ((long)E + 15) / 16;                      // 4 lanes per 16-edge group
    long sthreads = groups * 4;
    int sblocks = (int)((sthreads + 255) / 256);
    k_scatter<<<sblocks, 256>>>(src, dst, E);

    k_out<<<(N + 255) / 256, 512>>>(out, N);                // 256-node tiles
}

// round 17
// speedup vs baseline: 1.0435x; 1.0435x over previous
#include <cuda_runtime.h>

// GCN_75050258530542 — round 17: R15 base (best measured: 8-edge/4-lane
// scatter, 8-edge/thread degree) + k_out weights-in-registers (the one
// verified R16 gain). No other changes.
// out[n,:] = rsqrt(deg_in[n]) * (sum_{e:dst=n} x[src,15:25]*rsqrt(deg_out[src])) @ (W1@W2)
//            + (b1@W2 + b2)

constexpr int NMAX = 100000;
constexpr int FP   = 16;   // 64B rows, 128B-aligned: 4-lane group hits 1 line

__device__ int g_deg_out[NMAX];
__device__ __align__(128) float g_xsn[NMAX * FP];   // slots 0-9 = x[:,15:25]*norm_s; pad 0
__device__ __align__(128) float g_agg[NMAX * FP];   // slots 0-9 sums, slot 10 = deg_in
__device__ float g_Weff[640];                       // W1@W2 (10 x 64)
__device__ float g_beff[64];                        // b1@W2 + b2

// ---------------------------------------------------------------- degrees + weff (last block)
__global__ void k_deg_weff(const int* __restrict__ src, int E,
                           const float* __restrict__ W1, const float* __restrict__ b1,
                           const float* __restrict__ W2, const float* __restrict__ b2) {
    int nb = gridDim.x - 1;
    if ((int)blockIdx.x == nb) {
        for (int idx = threadIdx.x; idx < 704; idx += blockDim.x) {
            if (idx < 640) {
                int i = idx >> 6, j = idx & 63;
                float s = 0.f;
#pragma unroll 8
                for (int k = 0; k < 128; k++) s += W1[i * 128 + k] * W2[k * 64 + j];
                g_Weff[idx] = s;
            } else {
                int j = idx - 640;
                float s = b2[j];
#pragma unroll 8
                for (int k = 0; k < 128; k++) s += b1[k] * W2[k * 64 + j];
                g_beff[j] = s;
            }
        }
        return;
    }
    int n8 = E >> 3;
    int stride = nb * blockDim.x;
    for (int t = blockIdx.x * blockDim.x + threadIdx.x; t < n8; t += stride) {
        int4 s0 = reinterpret_cast<const int4*>(src)[2 * t];
        int4 s1 = reinterpret_cast<const int4*>(src)[2 * t + 1];
        atomicAdd(&g_deg_out[s0.x], 1);
        atomicAdd(&g_deg_out[s0.y], 1);
        atomicAdd(&g_deg_out[s0.z], 1);
        atomicAdd(&g_deg_out[s0.w], 1);
        atomicAdd(&g_deg_out[s1.x], 1);
        atomicAdd(&g_deg_out[s1.y], 1);
        atomicAdd(&g_deg_out[s1.z], 1);
        atomicAdd(&g_deg_out[s1.w], 1);
    }
    if (blockIdx.x == 0 && threadIdx.x == 0) {
        for (int e = (n8 << 3); e < E; e++) atomicAdd(&g_deg_out[src[e]], 1);
    }
}

// ---------------------------------------------------------------- prep: xsn = x[:,15:25]*norm_s + cleanup
__global__ void k_prep(const float* __restrict__ x, int N) {
    int i = blockIdx.x * blockDim.x + threadIdx.x;
    if (i >= N) return;
    int dout = g_deg_out[i];
    g_deg_out[i] = 0;                                   // self-clean (last reader)
    float ns = rsqrtf(dout > 0 ? (float)dout : 1.f);
    const float* base = x + (size_t)i * 40;
    float4 L0 = *reinterpret_cast<const float4*>(base + 12);
    float4 L1 = *reinterpret_cast<const float4*>(base + 16);
    float4 L2 = *reinterpret_cast<const float4*>(base + 20);
    float4 L3 = *reinterpret_cast<const float4*>(base + 24);
    float* o = g_xsn + (size_t)i * FP;
    *reinterpret_cast<float4*>(o)     = make_float4(L0.w * ns, L1.x * ns, L1.y * ns, L1.z * ns); // c15-18
    *reinterpret_cast<float4*>(o + 4) = make_float4(L1.w * ns, L2.x * ns, L2.y * ns, L2.z * ns); // c19-22
    *reinterpret_cast<float4*>(o + 8) = make_float4(L2.w * ns, L3.x * ns, 0.f, 0.f);             // c23-24, pad
    // zero this node's agg row for the upcoming scatter (idle store BW)
    float4 z = {0.f, 0.f, 0.f, 0.f};
    float4* a = reinterpret_cast<float4*>(g_agg + (size_t)i * FP);
    a[0] = z; a[1] = z; a[2] = z; a[3] = z;
}

// ---------------------------------------------------------------- vector RED
__device__ __forceinline__ void red4(float* p, float a, float b, float c, float d) {
    asm volatile("red.global.add.v4.f32 [%0], {%1,%2,%3,%4};"
                 :: "l"(p), "f"(a), "f"(b), "f"(c), "f"(d) : "memory");
}

// ---------------------------------------------------------------- scatter: 4 lanes/edge, 8 edges/group
__global__ void __launch_bounds__(256) k_scatter(const int* __restrict__ src,
                                                 const int* __restrict__ dst, int E) {
    int tid = blockIdx.x * blockDim.x + threadIdx.x;
    int g = tid >> 2;          // edge group (8 edges)
    int q = tid & 3;           // quarter within feature row
    long base = (long)g * 8;
    if (base >= E) return;

    unsigned am = 0xffffffffu;
    int full = (base + 8 <= (long)E);

    int dd[8];
    float4 v[8];
    if (full) {
        int s2a = __ldg(src + base + 2 * q);
        int s2b = __ldg(src + base + 2 * q + 1);
        int d2a = __ldg(dst + base + 2 * q);
        int d2b = __ldg(dst + base + 2 * q + 1);
        int lq = (tid & 31) & ~3;
#pragma unroll
        for (int j = 0; j < 8; j++) {
            int owner = lq + (j >> 1);
            int sj = __shfl_sync(am, (j & 1) ? s2b : s2a, owner);
            dd[j]  = __shfl_sync(am, (j & 1) ? d2b : d2a, owner);
            if (q < 3) v[j] = *reinterpret_cast<const float4*>(g_xsn + (size_t)sj * FP + q * 4);
        }
#pragma unroll
        for (int j = 0; j < 8; j++) {
            if (q < 3) {
                float4 p = v[j];
                if (q == 2) { p.z = 1.0f; p.w = 0.0f; }   // slot 10 += 1 (deg_in)
                red4(g_agg + (size_t)dd[j] * FP + q * 4, p.x, p.y, p.z, p.w);
            }
        }
    } else {
        int cnt = (int)(E - base);
        for (int j = 0; j < cnt; j++) {
            int sj = __ldg(src + base + j);
            int dj = __ldg(dst + base + j);
            if (q < 3) {
                float4 p = *reinterpret_cast<const float4*>(g_xsn + (size_t)sj * FP + q * 4);
                if (q == 2) { p.z = 1.0f; p.w = 0.0f; }
                red4(g_agg + (size_t)dj * FP + q * 4, p.x, p.y, p.z, p.w);
            }
        }
    }
}

// ---------------------------------------------------------------- k_out: 256-node smem tile, weights in regs
__global__ void __launch_bounds__(512) k_out(float* __restrict__ out, int N) {
    __shared__ __align__(16) float sAgg[256 * FP];   // 16KB tile
    int t = threadIdx.x;

    int tile = blockIdx.x * 256;
    int cnt = N - tile; if (cnt > 256) cnt = 256;
    int nq = cnt * 4;

    {
        const float4* srcA = reinterpret_cast<const float4*>(g_agg + (size_t)tile * FP);
        float4* dstA = reinterpret_cast<float4*>(sAgg);
        for (int k = t; k < nq; k += 512) dstA[k] = srcA[k];
    }

    int lane = t & 31;
    int warp = t >> 5;          // 16 warps
    // weights direct to registers: per k the warp reads 32 consecutive floats (1 line)
    float w0[10], w1[10];
#pragma unroll
    for (int k = 0; k < 10; k++) {
        w0[k] = g_Weff[k * 64 + lane];
        w1[k] = g_Weff[k * 64 + 32 + lane];
    }
    float b0 = g_beff[lane];
    float b1 = g_beff[lane + 32];
    __syncthreads();

    for (int i = warp; i < cnt; i += 16) {
        const float4* r = reinterpret_cast<const float4*>(sAgg + i * FP);
        float4 a0 = r[0], a1 = r[1], a2 = r[2];   // LDS broadcast
        float nd = rsqrtf(a2.z > 0.f ? a2.z : 1.f);
        float s0 = a0.x * w0[0] + a0.y * w0[1] + a0.z * w0[2] + a0.w * w0[3]
                 + a1.x * w0[4] + a1.y * w0[5] + a1.z * w0[6] + a1.w * w0[7]
                 + a2.x * w0[8] + a2.y * w0[9];
        float s1 = a0.x * w1[0] + a0.y * w1[1] + a0.z * w1[2] + a0.w * w1[3]
                 + a1.x * w1[4] + a1.y * w1[5] + a1.z * w1[6] + a1.w * w1[7]
                 + a2.x * w1[8] + a2.y * w1[9];
        float* orow = out + (size_t)(tile + i) * 64;
        orow[lane]      = b0 + nd * s0;
        orow[lane + 32] = b1 + nd * s1;
    }
}

// ---------------------------------------------------------------- launch
extern "C" void kernel_launch(void* const* d_in, const int* in_sizes, int n_in,
                              void* d_out, int out_size) {
    const float* x   = (const float*)d_in[0];
    const int*   src = (const int*)d_in[1];
    const int*   dst = (const int*)d_in[2];
    const float* W1  = (const float*)d_in[3];
    const float* b1  = (const float*)d_in[4];
    const float* W2  = (const float*)d_in[5];
    const float* b2  = (const float*)d_in[6];
    float* out = (float*)d_out;

    int N = in_sizes[0] / 40;
    int E = in_sizes[1];

    // self-cleaning scratch: k_prep zeroes g_deg_out + g_agg before the scatter.

    int n8 = E >> 3;
    int db = (n8 > 0 ? (n8 + 255) / 256 : 1) + 1;          // +1 block for weff
    k_deg_weff<<<db, 256>>>(src, E, W1, b1, W2, b2);
    k_prep<<<(N + 255) / 256, 256>>>(x, N);

    long groups = ((long)E + 7) / 8;                        // 4 lanes per 8-edge group
    long sthreads = groups * 4;
    int sblocks = (int)((sthreads + 255) / 256);
    k_scatter<<<sblocks, 256>>>(src, dst, E);

    k_out<<<(N + 255) / 256, 512>>>(out, N);                // 256-node tiles
}